// round 9
// baseline (speedup 1.0000x reference)
#include <cuda_runtime.h>

typedef unsigned long long ULL;

// ---------------- f32x2 helpers ----------------
__device__ __forceinline__ ULL pk2(float lo, float hi) {
    ULL r; asm("mov.b64 %0, {%1,%2};" : "=l"(r) : "f"(lo), "f"(hi)); return r;
}
__device__ __forceinline__ void upk2(ULL v, float& lo, float& hi) {
    asm("mov.b64 {%0,%1}, %2;" : "=f"(lo), "=f"(hi) : "l"(v));
}
__device__ __forceinline__ ULL fma2_(ULL a, ULL b, ULL c) {
    ULL d; asm("fma.rn.f32x2 %0, %1, %2, %3;" : "=l"(d) : "l"(a), "l"(b), "l"(c)); return d;
}

// ---------------- MUFU softplus + sigmoid (scalar) ----------------
// u = exp(-|x|) via MUFU.EX2; softplus = max(x,0) + lg2(1+u)*ln2 (MUFU.LG2);
// sigmoid = (x>=0 ? 1 : u) / (1+u) via MUFU.RCP. All approx err <= ~2^-21.
__device__ __forceinline__ void act1m(float x, float& sp, float& sg) {
    float u;
    asm("ex2.approx.f32 %0, %1;" : "=f"(u)
        : "f"(fabsf(x) * -1.4426950408889634f));
    float opu = 1.0f + u;
    float lg, r;
    asm("lg2.approx.f32 %0, %1;" : "=f"(lg) : "f"(opu));
    asm("rcp.approx.f32 %0, %1;" : "=f"(r)  : "f"(opu));
    sp = fmaxf(x, 0.0f) + lg * 0.69314718055994531f;
    sg = r * ((x >= 0.0f) ? 1.0f : u);
}

// ---------------- shared-memory layout ----------------
// w2g block per jp (output pair j2=2jp, 2jp+1): 64 ulonglong2 entries,
//   index jp*64 + k2*4 + slot, slot = {P(2jp), P(2jp+1), TW(2jp), TW(2jp+1)}
//   P  = W2[j2][1+4k2 .. +3]                                 (primal)
//   TW = P * (W3[0][1+j2]*W1[k][z0] + W3[1][1+j2]*W1[k][z1]) (folded tangent+W3)
// actsg: per-thread sigmoid activations [k-pair][tid], conflict-free LDS.64.
struct SmemW {
    ulonglong2 w2g[32 * 64];                     // 32768 B
    ULL actsg[32 * 128];                         // 32768 B (per-thread scratch)
    ULL w1t[32], w1z0[32], w1z1[32], w1b[32];    // layer-1, packed unit pairs
    ULL w2tb[64];                                // {W2[j][0], b2[j]}
    ULL w3r0[32], w3r1[32];                      // packed W3 rows (z_dot epilogue)
    float w3t0, w3t1, b30, b31;
};

// ---------------- one dynamics evaluation ----------------
__device__ __forceinline__ void eval_dyn(SmemW& sm, int tid, float t, float z0, float z1,
                                         float& k0, float& k1, float& kl)
{
    ULL s1p[32];            // packed softplus of layer-1 (regs); sigmoid -> smem
    ULL tp = pk2(t, t), z0p = pk2(z0, z0), z1p = pk2(z1, z1);
    #pragma unroll
    for (int k = 0; k < 32; ++k) {
        ULL x = fma2_(sm.w1t[k], tp, sm.w1b[k]);
        x = fma2_(sm.w1z0[k], z0p, x);
        x = fma2_(sm.w1z1[k], z1p, x);
        float xa, xb; upk2(x, xa, xb);
        float spa, sga, spb, sgb;
        act1m(xa, spa, sga);
        act1m(xb, spb, sgb);
        s1p[k] = pk2(spa, spb);
        sm.actsg[k * 128 + tid] = pk2(sga, sgb);   // private column, no sync
    }

    ULL Zd0 = 0ull, Zd1 = 0ull, Tr = 0ull;   // bit pattern 0 == {0.f, 0.f}

    // Tile of 4 output-unit pairs (8 units): activation loads amortized x4.
    #pragma unroll 1
    for (int jt = 0; jt < 8; ++jt) {
        ULL accp[8], acct[8];
        #pragma unroll
        for (int u = 0; u < 8; ++u) { accp[u] = 0ull; acct[u] = 0ull; }
        const ulonglong2* rb = &sm.w2g[jt * 256];
        #pragma unroll
        for (int k2 = 0; k2 < 16; ++k2) {
            ULL se = s1p[2 * k2], so = s1p[2 * k2 + 1];
            ULL ge = sm.actsg[(2 * k2) * 128 + tid];
            ULL go = sm.actsg[(2 * k2 + 1) * 128 + tid];
            #pragma unroll
            for (int u = 0; u < 4; ++u) {
                const ulonglong2* r = &rb[u * 64 + k2 * 4];
                ulonglong2 P0 = r[0];
                ulonglong2 P1 = r[1];
                ulonglong2 T0 = r[2];
                ulonglong2 T1 = r[3];
                accp[2*u]   = fma2_(P0.x, se, accp[2*u]);
                accp[2*u]   = fma2_(P0.y, so, accp[2*u]);
                accp[2*u+1] = fma2_(P1.x, se, accp[2*u+1]);
                accp[2*u+1] = fma2_(P1.y, so, accp[2*u+1]);
                acct[2*u]   = fma2_(T0.x, ge, acct[2*u]);
                acct[2*u]   = fma2_(T0.y, go, acct[2*u]);
                acct[2*u+1] = fma2_(T1.x, ge, acct[2*u+1]);
                acct[2*u+1] = fma2_(T1.y, go, acct[2*u+1]);
            }
        }
        #pragma unroll
        for (int u = 0; u < 4; ++u) {
            int jp = jt * 4 + u;
            float w2ta, b2a; upk2(sm.w2tb[2 * jp],     w2ta, b2a);
            float w2tc, b2c; upk2(sm.w2tb[2 * jp + 1], w2tc, b2c);
            float pl, ph;
            upk2(accp[2*u],   pl, ph); float h20 = pl + ph + fmaf(w2ta, t, b2a);
            upk2(accp[2*u+1], pl, ph); float h21 = pl + ph + fmaf(w2tc, t, b2c);
            upk2(acct[2*u],   pl, ph); float td0 = pl + ph;
            upk2(acct[2*u+1], pl, ph); float td1 = pl + ph;
            float sp0, sg0, sp1, sg1;
            act1m(h20, sp0, sg0);
            act1m(h21, sp1, sg1);
            ULL sp2 = pk2(sp0, sp1);
            Zd0 = fma2_(sm.w3r0[jp], sp2, Zd0);
            Zd1 = fma2_(sm.w3r1[jp], sp2, Zd1);
            Tr  = fma2_(pk2(sg0, sg1), pk2(td0, td1), Tr);
        }
    }
    float a, b;
    upk2(Zd0, a, b); k0 = a + b + fmaf(sm.w3t0, t, sm.b30);
    upk2(Zd1, a, b); k1 = a + b + fmaf(sm.w3t1, t, sm.b31);
    upk2(Tr,  a, b); kl = -(a + b);
}

__global__ void __launch_bounds__(128, 3) ffjord_kernel(
    const float2* __restrict__ zin, const float* __restrict__ dlp,
    const float* __restrict__ W1, const float* __restrict__ b1,
    const float* __restrict__ W2, const float* __restrict__ b2,
    const float* __restrict__ W3, const float* __restrict__ b3,
    float* __restrict__ out, int B)
{
    extern __shared__ unsigned char smraw[];
    SmemW& sm = *reinterpret_cast<SmemW*>(smraw);
    int tid = threadIdx.x;

    // ---- stage weights into smem ----
    for (int idx = tid; idx < 2048; idx += 128) {
        int jp   = idx >> 6;
        int rem  = idx & 63;
        int k2   = rem >> 2;
        int slot = rem & 3;
        int j2   = 2 * jp + (slot & 1);
        int bb   = 4 * k2;
        const float* wr = W2 + j2 * 65 + 1;          // skip time column
        float p0 = wr[bb + 0], p1 = wr[bb + 1], p2 = wr[bb + 2], p3 = wr[bb + 3];
        ulonglong2 E;
        if (slot < 2) {
            E.x = pk2(p0, p1); E.y = pk2(p2, p3);
        } else {
            float w30 = W3[1 + j2], w31 = W3[66 + j2];
            float t0 = fmaf(w30, W1[(bb + 0) * 3 + 1], w31 * W1[(bb + 0) * 3 + 2]);
            float t1 = fmaf(w30, W1[(bb + 1) * 3 + 1], w31 * W1[(bb + 1) * 3 + 2]);
            float t2 = fmaf(w30, W1[(bb + 2) * 3 + 1], w31 * W1[(bb + 2) * 3 + 2]);
            float t3 = fmaf(w30, W1[(bb + 3) * 3 + 1], w31 * W1[(bb + 3) * 3 + 2]);
            E.x = pk2(p0 * t0, p1 * t1); E.y = pk2(p2 * t2, p3 * t3);
        }
        sm.w2g[idx] = E;
    }
    if (tid < 32) {
        int k = tid;                                  // unit pair (2k, 2k+1)
        sm.w1t[k]  = pk2(W1[(2 * k) * 3 + 0], W1[(2 * k + 1) * 3 + 0]);
        sm.w1z0[k] = pk2(W1[(2 * k) * 3 + 1], W1[(2 * k + 1) * 3 + 1]);
        sm.w1z1[k] = pk2(W1[(2 * k) * 3 + 2], W1[(2 * k + 1) * 3 + 2]);
        sm.w1b[k]  = pk2(b1[2 * k], b1[2 * k + 1]);
        sm.w3r0[k] = pk2(W3[1 + 2 * k],  W3[2 + 2 * k]);
        sm.w3r1[k] = pk2(W3[66 + 2 * k], W3[67 + 2 * k]);
    } else if (tid < 96) {
        int j = tid - 32;
        sm.w2tb[j] = pk2(W2[j * 65 + 0], b2[j]);
    }
    if (tid == 0) { sm.w3t0 = W3[0]; sm.w3t1 = W3[65]; sm.b30 = b3[0]; sm.b31 = b3[1]; }
    __syncthreads();

    int gid = blockIdx.x * 128 + tid;
    if (gid >= B) return;
    float2 zv = zin[gid];
    float z0 = zv.x, z1 = zv.y;
    float lp = dlp[gid];

    const float dt = 0.25f;
    #pragma unroll 1
    for (int step = 0; step < 4; ++step) {
        float tb = (float)step * dt;
        float acc0 = 0.0f, acc1 = 0.0f, accl = 0.0f;
        float pk0v = 0.0f, pk1v = 0.0f;
        #pragma unroll 1
        for (int s = 0; s < 4; ++s) {
            float cs = (s == 0) ? 0.0f : ((s == 3) ? dt : 0.5f * dt);
            float ws = (s == 1 || s == 2) ? 2.0f : 1.0f;
            float te = tb + cs;
            float i0 = fmaf(cs, pk0v, z0);
            float i1 = fmaf(cs, pk1v, z1);
            float k0, k1, klv;
            eval_dyn(sm, tid, te, i0, i1, k0, k1, klv);
            acc0 = fmaf(ws, k0, acc0);
            acc1 = fmaf(ws, k1, acc1);
            accl = fmaf(ws, klv, accl);
            pk0v = k0; pk1v = k1;
        }
        const float c6 = dt / 6.0f;
        z0 = fmaf(c6, acc0, z0);
        z1 = fmaf(c6, acc1, z1);
        lp = fmaf(c6, accl, lp);
    }

    reinterpret_cast<float2*>(out)[gid] = make_float2(z0, z1);  // zf: (B,2)
    out[2 * B + gid] = lp;                                      // delta_logpz: (B,1)
}

extern "C" void kernel_launch(void* const* d_in, const int* in_sizes, int n_in,
                              void* d_out, int out_size) {
    const float2* z  = (const float2*)d_in[0];
    const float* dlp = (const float*)d_in[1];
    const float* W1  = (const float*)d_in[2];
    const float* b1  = (const float*)d_in[3];
    const float* W2  = (const float*)d_in[4];
    const float* b2  = (const float*)d_in[5];
    const float* W3  = (const float*)d_in[6];
    const float* b3  = (const float*)d_in[7];
    float* out = (float*)d_out;
    int B = in_sizes[0] / 2;

    // Host-side, enqueues nothing -> graph-capture safe. Idempotent.
    cudaFuncSetAttribute(ffjord_kernel, cudaFuncAttributeMaxDynamicSharedMemorySize,
                         (int)sizeof(SmemW));

    int blocks = (B + 127) / 128;
    ffjord_kernel<<<blocks, 128, sizeof(SmemW)>>>(z, dlp, W1, b1, W2, b2, W3, b3, out, B);
}

// round 11
// speedup vs baseline: 4.7098x; 4.7098x over previous
#include <cuda_runtime.h>
#include <cuda_fp16.h>

typedef unsigned long long ULL;
typedef unsigned int u32;

// ---------------- f32x2 helpers ----------------
__device__ __forceinline__ ULL pk2(float lo, float hi) {
    ULL r; asm("mov.b64 %0, {%1,%2};" : "=l"(r) : "f"(lo), "f"(hi)); return r;
}
__device__ __forceinline__ void upk2(ULL v, float& lo, float& hi) {
    asm("mov.b64 {%0,%1}, %2;" : "=f"(lo), "=f"(hi) : "l"(v));
}
__device__ __forceinline__ ULL fma2_(ULL a, ULL b, ULL c) {
    ULL d; asm("fma.rn.f32x2 %0, %1, %2, %3;" : "=l"(d) : "l"(a), "l"(b), "l"(c)); return d;
}
__device__ __forceinline__ ULL add2_(ULL a, ULL b) {
    ULL d; asm("add.rn.f32x2 %0, %1, %2;" : "=l"(d) : "l"(a), "l"(b)); return d;
}
__device__ __forceinline__ ULL mul2_(ULL a, ULL b) {
    ULL d; asm("mul.rn.f32x2 %0, %1, %2;" : "=l"(d) : "l"(a), "l"(b)); return d;
}

// fp16 pack/unpack (lo -> low half)
__device__ __forceinline__ u32 f22h2(float lo, float hi) {
    __half2 h = __floats2half2_rn(lo, hi);
    return *reinterpret_cast<u32*>(&h);
}
__device__ __forceinline__ float2 h22f2(u32 v) {
    __half2 h = *reinterpret_cast<__half2*>(&v);
    return __half22float2(h);
}

// ---------------- packed MUFU-free softplus + sigmoid (R6, known-good) ----------------
__device__ __forceinline__ void act2(float xa, float xb, ULL& sp, ULL& sg)
{
    const ULL MAGIC = pk2(12582912.f, 12582912.f);
    const ULL NEG1  = pk2(-1.f, -1.f);
    const ULL ONE   = pk2(1.f, 1.f);
    const ULL TWO   = pk2(2.f, 2.f);
    const ULL C5 = pk2(1.33335581e-3f, 1.33335581e-3f);
    const ULL C4 = pk2(9.61812910e-3f, 9.61812910e-3f);
    const ULL C3 = pk2(5.55041087e-2f, 5.55041087e-2f);
    const ULL C2 = pk2(2.40226507e-1f, 2.40226507e-1f);
    const ULL C1 = pk2(6.93147182e-1f, 6.93147182e-1f);
    const ULL RI1 = pk2(-0.5f, -0.5f);
    const ULL RK1 = pk2(1.45710678f, 1.45710678f);
    const ULL RI2 = pk2(-0.16666667f, -0.16666667f);
    const ULL RK2 = pk2(0.82491498f, 0.82491498f);
    const ULL A7 = pk2(0.14285714f, 0.14285714f);
    const ULL A5 = pk2(0.2f, 0.2f);
    const ULL A3 = pk2(0.33333333f, 0.33333333f);

    float ya = fmaxf(fabsf(xa) * -1.4426950408889634f, -116.0f);
    float yb = fmaxf(fabsf(xb) * -1.4426950408889634f, -116.0f);
    ULL y  = pk2(ya, yb);
    ULL zz = add2_(y, MAGIC);
    ULL nf = fma2_(MAGIC, NEG1, zz);
    ULL f  = fma2_(nf, NEG1, y);
    float za, zb2; upk2(zz, za, zb2);
    int ia = __float_as_int(za), ibt = __float_as_int(zb2);
    float sa = __int_as_float((int)(((unsigned)(ia  + (127 - 0x4B400000))) << 23));
    float sb = __int_as_float((int)(((unsigned)(ibt + (127 - 0x4B400000))) << 23));
    ULL scale = pk2(sa, sb);
    ULL p = fma2_(C5, f, C4);
    p = fma2_(p, f, C3);
    p = fma2_(p, f, C2);
    p = fma2_(p, f, C1);
    p = fma2_(p, f, ONE);
    ULL u = mul2_(p, scale);
    ULL d1 = add2_(u, ONE);
    ULL r1 = fma2_(d1, RI1, RK1);
    ULL nd1 = mul2_(d1, NEG1);
    ULL m;
    m = fma2_(nd1, r1, TWO); r1 = mul2_(r1, m);
    m = fma2_(nd1, r1, TWO); r1 = mul2_(r1, m);
    ULL d2 = add2_(u, TWO);
    ULL r2 = fma2_(d2, RI2, RK2);
    ULL nd2 = mul2_(d2, NEG1);
    m = fma2_(nd2, r2, TWO); r2 = mul2_(r2, m);
    m = fma2_(nd2, r2, TWO); r2 = mul2_(r2, m);
    ULL s  = mul2_(u, r2);
    ULL s2 = mul2_(s, s);
    ULL q = fma2_(A7, s2, A5);
    q = fma2_(q, s2, A3);
    q = fma2_(q, s2, ONE);
    ULL l1p = mul2_(add2_(s, s), q);
    float mxa = fmaxf(xa, 0.f), mxb = fmaxf(xb, 0.f);
    sp = add2_(pk2(mxa, mxb), l1p);
    float ulo, uhi; upk2(u, ulo, uhi);
    float ga = (xa >= 0.f) ? 1.f : ulo;
    float gb = (xb >= 0.f) ? 1.f : uhi;
    sg = mul2_(r1, pk2(ga, gb));
}

// m16n8k16 fp16 -> f32 MMA (generic target HMMA; NOT tcgen05)
#define MMA16816(d0,d1,d2,d3,a0,a1,a2,a3,b0,b1) \
    asm volatile("mma.sync.aligned.m16n8k16.row.col.f32.f16.f16.f32 " \
        "{%0,%1,%2,%3}, {%4,%5,%6,%7}, {%8,%9}, {%0,%1,%2,%3};" \
        : "+f"(d0), "+f"(d1), "+f"(d2), "+f"(d3) \
        : "r"(a0), "r"(a1), "r"(a2), "r"(a3), "r"(b0), "r"(b1))

// ---------------- smem layout (byte offsets; pitch 144B keeps LDS conflict-free) ----
static constexpr int PITCH   = 144;              // 64 fp16 = 128B + 16B pad
static constexpr int A_SPHI  = 0;                // acts softplus hi [128 rows]
static constexpr int A_SPLO  = 18432;            // softplus lo
static constexpr int A_SGHI  = 36864;            // sigmoid  hi
static constexpr int A_SGLO  = 55296;            // sigmoid  lo
static constexpr int B_PHI   = 73728;            // W2 primal hi   [64 rows n][k]
static constexpr int B_PLO   = 82944;            // W2 primal lo
static constexpr int B_THI   = 92160;            // folded tangent hi
static constexpr int B_TLO   = 101376;           // folded tangent lo
static constexpr int W1T_O   = 110592, W1Z0_O = 110848, W1Z1_O = 111104, W1B_O = 111360;
static constexpr int COLW_O  = 111616;           // float4[64] {w2t, b2, w30, w31}
static constexpr int SCAL_O  = 112640;           // float4 {W3[0][0], W3[1][0], b3[0], b3[1]}
static constexpr int SMEM_BYTES = 112656;

__global__ void __launch_bounds__(128, 2) ffjord_mma_kernel(
    const float2* __restrict__ zin, const float* __restrict__ dlp,
    const float* __restrict__ W1, const float* __restrict__ b1,
    const float* __restrict__ W2, const float* __restrict__ b2,
    const float* __restrict__ W3, const float* __restrict__ b3,
    float* __restrict__ out, int B)
{
    extern __shared__ __align__(16) unsigned char smraw[];
    int tid = threadIdx.x;
    int lane = tid & 31, warp = tid >> 5;
    int g = lane >> 2, t4 = lane & 3;

    // ---- stage B weight tiles (fp16 hi/lo split) ----
    if (tid < 64) {
        int j = tid;
        float w30 = W3[1 + j], w31 = W3[66 + j];
        for (int k = 0; k < 64; ++k) {
            float p  = W2[j * 65 + 1 + k];
            float tw = p * fmaf(w30, W1[k * 3 + 1], w31 * W1[k * 3 + 2]);
            __half ph = __float2half_rn(p);
            __half pl = __float2half_rn(p - __half2float(ph));
            __half th = __float2half_rn(tw);
            __half tl = __float2half_rn(tw - __half2float(th));
            int off = j * PITCH + k * 2;
            *(__half*)(smraw + B_PHI + off) = ph;
            *(__half*)(smraw + B_PLO + off) = pl;
            *(__half*)(smraw + B_THI + off) = th;
            *(__half*)(smraw + B_TLO + off) = tl;
        }
    }
    if (tid < 32) {
        int k = tid;   // unit pair (2k, 2k+1)
        ((ULL*)(smraw + W1T_O))[k]  = pk2(W1[(2 * k) * 3 + 0], W1[(2 * k + 1) * 3 + 0]);
        ((ULL*)(smraw + W1Z0_O))[k] = pk2(W1[(2 * k) * 3 + 1], W1[(2 * k + 1) * 3 + 1]);
        ((ULL*)(smraw + W1Z1_O))[k] = pk2(W1[(2 * k) * 3 + 2], W1[(2 * k + 1) * 3 + 2]);
        ((ULL*)(smraw + W1B_O))[k]  = pk2(b1[2 * k], b1[2 * k + 1]);
    } else if (tid >= 64) {
        int j = tid - 64;
        ((float4*)(smraw + COLW_O))[j] =
            make_float4(W2[j * 65 + 0], b2[j], W3[1 + j], W3[66 + j]);
    }
    if (tid == 0)
        *(float4*)(smraw + SCAL_O) = make_float4(W3[0], W3[65], b3[0], b3[1]);
    __syncthreads();

    const ULL* w1t  = (const ULL*)(smraw + W1T_O);
    const ULL* w1z0 = (const ULL*)(smraw + W1Z0_O);
    const ULL* w1z1 = (const ULL*)(smraw + W1Z1_O);
    const ULL* w1b  = (const ULL*)(smraw + W1B_O);
    const float4* colw = (const float4*)(smraw + COLW_O);
    float4 scal = *(const float4*)(smraw + SCAL_O);

    int gid = blockIdx.x * 128 + tid;
    int gidc = (gid < B) ? gid : (B - 1);
    float2 zv = zin[gidc];
    float z0 = zv.x, z1 = zv.y;
    float lp = dlp[gidc];

    const int rowoff = tid * PITCH;

    const float dt = 0.25f;
    #pragma unroll 1
    for (int step = 0; step < 4; ++step) {
        float tbv = (float)step * dt;
        float acc0 = 0.f, acc1 = 0.f, accl = 0.f;
        float pk0v = 0.f, pk1v = 0.f;
        #pragma unroll 1
        for (int s = 0; s < 4; ++s) {
            float cs = (s == 0) ? 0.0f : ((s == 3) ? dt : 0.5f * dt);
            float ws = (s == 1 || s == 2) ? 2.0f : 1.0f;
            float te = tbv + cs;
            float i0 = fmaf(cs, pk0v, z0);
            float i1 = fmaf(cs, pk1v, z1);

            // ---- layer 1: acts for this thread's sample row -> smem (fp16 hi/lo)
            ULL tp = pk2(te, te), z0p = pk2(i0, i0), z1p = pk2(i1, i1);
            #pragma unroll 1
            for (int kq = 0; kq < 8; ++kq) {
                u32 sph[4], spl[4], sgh[4], sgl[4];
                #pragma unroll
                for (int q = 0; q < 4; ++q) {
                    int kp = kq * 4 + q;
                    ULL x = fma2_(w1t[kp], tp, w1b[kp]);
                    x = fma2_(w1z0[kp], z0p, x);
                    x = fma2_(w1z1[kp], z1p, x);
                    float xa, xb; upk2(x, xa, xb);
                    ULL sp, sg; act2(xa, xb, sp, sg);
                    float spa, spb, sga, sgb;
                    upk2(sp, spa, spb); upk2(sg, sga, sgb);
                    sph[q] = f22h2(spa, spb);
                    float2 r = h22f2(sph[q]);
                    spl[q] = f22h2(spa - r.x, spb - r.y);
                    sgh[q] = f22h2(sga, sgb);
                    float2 r2 = h22f2(sgh[q]);
                    sgl[q] = f22h2(sga - r2.x, sgb - r2.y);
                }
                int co = rowoff + kq * 16;
                *(uint4*)(smraw + A_SPHI + co) = make_uint4(sph[0], sph[1], sph[2], sph[3]);
                *(uint4*)(smraw + A_SPLO + co) = make_uint4(spl[0], spl[1], spl[2], spl[3]);
                *(uint4*)(smraw + A_SGHI + co) = make_uint4(sgh[0], sgh[1], sgh[2], sgh[3]);
                *(uint4*)(smraw + A_SGLO + co) = make_uint4(sgl[0], sgl[1], sgl[2], sgl[3]);
            }
            __syncwarp();

            // ---- load A fragments (persistent in registers) ----
            u32 aSPH[32], aSPL[32], aSGH[32], aSGL[32];
            #pragma unroll
            for (int mm = 0; mm < 2; ++mm) {
                #pragma unroll
                for (int k = 0; k < 4; ++k) {
                    int r0b = (warp * 32 + mm * 16 + g) * PITCH + k * 32 + t4 * 4;
                    int r1b = r0b + 8 * PITCH;
                    int fi = (mm * 4 + k) * 4;
                    aSPH[fi+0] = *(const u32*)(smraw + A_SPHI + r0b);
                    aSPH[fi+1] = *(const u32*)(smraw + A_SPHI + r1b);
                    aSPH[fi+2] = *(const u32*)(smraw + A_SPHI + r0b + 16);
                    aSPH[fi+3] = *(const u32*)(smraw + A_SPHI + r1b + 16);
                    aSPL[fi+0] = *(const u32*)(smraw + A_SPLO + r0b);
                    aSPL[fi+1] = *(const u32*)(smraw + A_SPLO + r1b);
                    aSPL[fi+2] = *(const u32*)(smraw + A_SPLO + r0b + 16);
                    aSPL[fi+3] = *(const u32*)(smraw + A_SPLO + r1b + 16);
                    aSGH[fi+0] = *(const u32*)(smraw + A_SGHI + r0b);
                    aSGH[fi+1] = *(const u32*)(smraw + A_SGHI + r1b);
                    aSGH[fi+2] = *(const u32*)(smraw + A_SGHI + r0b + 16);
                    aSGH[fi+3] = *(const u32*)(smraw + A_SGHI + r1b + 16);
                    aSGL[fi+0] = *(const u32*)(smraw + A_SGLO + r0b);
                    aSGL[fi+1] = *(const u32*)(smraw + A_SGLO + r1b);
                    aSGL[fi+2] = *(const u32*)(smraw + A_SGLO + r0b + 16);
                    aSGL[fi+3] = *(const u32*)(smraw + A_SGLO + r1b + 16);
                }
            }

            float zr0[4] = {0.f, 0.f, 0.f, 0.f};
            float zr1[4] = {0.f, 0.f, 0.f, 0.f};
            float trr[4] = {0.f, 0.f, 0.f, 0.f};

            #pragma unroll 1
            for (int n = 0; n < 8; ++n) {
                float dP[2][4] = {{0.f,0.f,0.f,0.f},{0.f,0.f,0.f,0.f}};
                float dT[2][4] = {{0.f,0.f,0.f,0.f},{0.f,0.f,0.f,0.f}};
                #pragma unroll
                for (int k = 0; k < 4; ++k) {
                    int bb = (n * 8 + g) * PITCH + k * 32 + t4 * 4;
                    u32 pbh0 = *(const u32*)(smraw + B_PHI + bb);
                    u32 pbh1 = *(const u32*)(smraw + B_PHI + bb + 16);
                    u32 pbl0 = *(const u32*)(smraw + B_PLO + bb);
                    u32 pbl1 = *(const u32*)(smraw + B_PLO + bb + 16);
                    u32 tbh0 = *(const u32*)(smraw + B_THI + bb);
                    u32 tbh1 = *(const u32*)(smraw + B_THI + bb + 16);
                    u32 tbl0 = *(const u32*)(smraw + B_TLO + bb);
                    u32 tbl1 = *(const u32*)(smraw + B_TLO + bb + 16);
                    #pragma unroll
                    for (int mm = 0; mm < 2; ++mm) {
                        int fi = (mm * 4 + k) * 4;
                        MMA16816(dP[mm][0],dP[mm][1],dP[mm][2],dP[mm][3],
                                 aSPH[fi],aSPH[fi+1],aSPH[fi+2],aSPH[fi+3], pbh0,pbh1);
                        MMA16816(dP[mm][0],dP[mm][1],dP[mm][2],dP[mm][3],
                                 aSPL[fi],aSPL[fi+1],aSPL[fi+2],aSPL[fi+3], pbh0,pbh1);
                        MMA16816(dP[mm][0],dP[mm][1],dP[mm][2],dP[mm][3],
                                 aSPH[fi],aSPH[fi+1],aSPH[fi+2],aSPH[fi+3], pbl0,pbl1);
                        MMA16816(dT[mm][0],dT[mm][1],dT[mm][2],dT[mm][3],
                                 aSGH[fi],aSGH[fi+1],aSGH[fi+2],aSGH[fi+3], tbh0,tbh1);
                        MMA16816(dT[mm][0],dT[mm][1],dT[mm][2],dT[mm][3],
                                 aSGL[fi],aSGL[fi+1],aSGL[fi+2],aSGL[fi+3], tbh0,tbh1);
                        MMA16816(dT[mm][0],dT[mm][1],dT[mm][2],dT[mm][3],
                                 aSGH[fi],aSGH[fi+1],aSGH[fi+2],aSGH[fi+3], tbl0,tbl1);
                    }
                }
                // epilogue for this n-tile: cols c0 = n*8+2t4, c0+1
                int c0 = n * 8 + 2 * t4;
                float4 cw0 = colw[c0];
                float4 cw1 = colw[c0 + 1];
                float hb0 = fmaf(cw0.x, te, cw0.y);
                float hb1 = fmaf(cw1.x, te, cw1.y);
                #pragma unroll
                for (int mm = 0; mm < 2; ++mm) {
                    ULL sp2, sg2;
                    float spa, spb, sga, sgb;
                    act2(dP[mm][0] + hb0, dP[mm][1] + hb1, sp2, sg2);
                    upk2(sp2, spa, spb); upk2(sg2, sga, sgb);
                    zr0[2*mm] = fmaf(cw0.z, spa, zr0[2*mm]);
                    zr0[2*mm] = fmaf(cw1.z, spb, zr0[2*mm]);
                    zr1[2*mm] = fmaf(cw0.w, spa, zr1[2*mm]);
                    zr1[2*mm] = fmaf(cw1.w, spb, zr1[2*mm]);
                    trr[2*mm] = fmaf(sga, dT[mm][0], trr[2*mm]);
                    trr[2*mm] = fmaf(sgb, dT[mm][1], trr[2*mm]);
                    act2(dP[mm][2] + hb0, dP[mm][3] + hb1, sp2, sg2);
                    upk2(sp2, spa, spb); upk2(sg2, sga, sgb);
                    zr0[2*mm+1] = fmaf(cw0.z, spa, zr0[2*mm+1]);
                    zr0[2*mm+1] = fmaf(cw1.z, spb, zr0[2*mm+1]);
                    zr1[2*mm+1] = fmaf(cw0.w, spa, zr1[2*mm+1]);
                    zr1[2*mm+1] = fmaf(cw1.w, spb, zr1[2*mm+1]);
                    trr[2*mm+1] = fmaf(sga, dT[mm][2], trr[2*mm+1]);
                    trr[2*mm+1] = fmaf(sgb, dT[mm][3], trr[2*mm+1]);
                }
            }

            // ---- quad reduction via per-warp smem scratch (aliases consumed A rows)
            // zr index r4 holds within-warp row (8*r4 + g); lanes t4 hold col partials.
            unsigned char* red = smraw + A_SPHI + warp * 32 * PITCH;
            #pragma unroll
            for (int r4 = 0; r4 < 4; ++r4) {
                int row = r4 * 8 + g;
                float* pr = (float*)(red + row * 48 + t4 * 12);
                pr[0] = zr0[r4]; pr[1] = zr1[r4]; pr[2] = trr[r4];
            }
            __syncwarp();
            float s0 = 0.f, s1 = 0.f, stv = 0.f;
            #pragma unroll
            for (int q = 0; q < 4; ++q) {
                const float* pr = (const float*)(red + lane * 48 + q * 12);
                s0 += pr[0]; s1 += pr[1]; stv += pr[2];
            }
            __syncwarp();

            float k0 = s0 + fmaf(scal.x, te, scal.z);
            float k1 = s1 + fmaf(scal.y, te, scal.w);
            float klv = -stv;

            acc0 = fmaf(ws, k0, acc0);
            acc1 = fmaf(ws, k1, acc1);
            accl = fmaf(ws, klv, accl);
            pk0v = k0; pk1v = k1;
        }
        const float c6 = dt / 6.0f;
        z0 = fmaf(c6, acc0, z0);
        z1 = fmaf(c6, acc1, z1);
        lp = fmaf(c6, accl, lp);
    }

    if (gid < B) {
        reinterpret_cast<float2*>(out)[gid] = make_float2(z0, z1);  // zf: (B,2)
        out[2 * B + gid] = lp;                                      // delta_logpz: (B,1)
    }
}

extern "C" void kernel_launch(void* const* d_in, const int* in_sizes, int n_in,
                              void* d_out, int out_size) {
    const float2* z  = (const float2*)d_in[0];
    const float* dlp = (const float*)d_in[1];
    const float* W1  = (const float*)d_in[2];
    const float* b1  = (const float*)d_in[3];
    const float* W2  = (const float*)d_in[4];
    const float* b2  = (const float*)d_in[5];
    const float* W3  = (const float*)d_in[6];
    const float* b3  = (const float*)d_in[7];
    float* out = (float*)d_out;
    int B = in_sizes[0] / 2;

    // Host-side, enqueues nothing -> graph-capture safe. Idempotent.
    cudaFuncSetAttribute(ffjord_mma_kernel, cudaFuncAttributeMaxDynamicSharedMemorySize,
                         SMEM_BYTES);

    int blocks = (B + 127) / 128;
    ffjord_mma_kernel<<<blocks, 128, SMEM_BYTES>>>(z, dlp, W1, b1, W2, b2, W3, b3, out, B);
}

// round 12
// speedup vs baseline: 6.1332x; 1.3022x over previous
#include <cuda_runtime.h>
#include <cuda_fp16.h>

typedef unsigned long long ULL;
typedef unsigned int u32;

// ---------------- f32x2 helpers ----------------
__device__ __forceinline__ ULL pk2(float lo, float hi) {
    ULL r; asm("mov.b64 %0, {%1,%2};" : "=l"(r) : "f"(lo), "f"(hi)); return r;
}
__device__ __forceinline__ void upk2(ULL v, float& lo, float& hi) {
    asm("mov.b64 {%0,%1}, %2;" : "=f"(lo), "=f"(hi) : "l"(v));
}
__device__ __forceinline__ ULL fma2_(ULL a, ULL b, ULL c) {
    ULL d; asm("fma.rn.f32x2 %0, %1, %2, %3;" : "=l"(d) : "l"(a), "l"(b), "l"(c)); return d;
}
__device__ __forceinline__ ULL add2_(ULL a, ULL b) {
    ULL d; asm("add.rn.f32x2 %0, %1, %2;" : "=l"(d) : "l"(a), "l"(b)); return d;
}
__device__ __forceinline__ ULL mul2_(ULL a, ULL b) {
    ULL d; asm("mul.rn.f32x2 %0, %1, %2;" : "=l"(d) : "l"(a), "l"(b)); return d;
}

// fp16 pack (lo -> low half)
__device__ __forceinline__ u32 f22h2(float lo, float hi) {
    __half2 h = __floats2half2_rn(lo, hi);
    return *reinterpret_cast<u32*>(&h);
}

// ---------------- packed MUFU-free softplus + sigmoid (R6, known-good) ----------------
__device__ __forceinline__ void act2(float xa, float xb, ULL& sp, ULL& sg)
{
    const ULL MAGIC = pk2(12582912.f, 12582912.f);
    const ULL NEG1  = pk2(-1.f, -1.f);
    const ULL ONE   = pk2(1.f, 1.f);
    const ULL TWO   = pk2(2.f, 2.f);
    const ULL C5 = pk2(1.33335581e-3f, 1.33335581e-3f);
    const ULL C4 = pk2(9.61812910e-3f, 9.61812910e-3f);
    const ULL C3 = pk2(5.55041087e-2f, 5.55041087e-2f);
    const ULL C2 = pk2(2.40226507e-1f, 2.40226507e-1f);
    const ULL C1 = pk2(6.93147182e-1f, 6.93147182e-1f);
    const ULL RI1 = pk2(-0.5f, -0.5f);
    const ULL RK1 = pk2(1.45710678f, 1.45710678f);
    const ULL RI2 = pk2(-0.16666667f, -0.16666667f);
    const ULL RK2 = pk2(0.82491498f, 0.82491498f);
    const ULL A7 = pk2(0.14285714f, 0.14285714f);
    const ULL A5 = pk2(0.2f, 0.2f);
    const ULL A3 = pk2(0.33333333f, 0.33333333f);

    float ya = fmaxf(fabsf(xa) * -1.4426950408889634f, -116.0f);
    float yb = fmaxf(fabsf(xb) * -1.4426950408889634f, -116.0f);
    ULL y  = pk2(ya, yb);
    ULL zz = add2_(y, MAGIC);
    ULL nf = fma2_(MAGIC, NEG1, zz);
    ULL f  = fma2_(nf, NEG1, y);
    float za, zb2; upk2(zz, za, zb2);
    int ia = __float_as_int(za), ibt = __float_as_int(zb2);
    float sa = __int_as_float((int)(((unsigned)(ia  + (127 - 0x4B400000))) << 23));
    float sb = __int_as_float((int)(((unsigned)(ibt + (127 - 0x4B400000))) << 23));
    ULL scale = pk2(sa, sb);
    ULL p = fma2_(C5, f, C4);
    p = fma2_(p, f, C3);
    p = fma2_(p, f, C2);
    p = fma2_(p, f, C1);
    p = fma2_(p, f, ONE);
    ULL u = mul2_(p, scale);
    ULL d1 = add2_(u, ONE);
    ULL r1 = fma2_(d1, RI1, RK1);
    ULL nd1 = mul2_(d1, NEG1);
    ULL m;
    m = fma2_(nd1, r1, TWO); r1 = mul2_(r1, m);
    m = fma2_(nd1, r1, TWO); r1 = mul2_(r1, m);
    ULL d2 = add2_(u, TWO);
    ULL r2 = fma2_(d2, RI2, RK2);
    ULL nd2 = mul2_(d2, NEG1);
    m = fma2_(nd2, r2, TWO); r2 = mul2_(r2, m);
    m = fma2_(nd2, r2, TWO); r2 = mul2_(r2, m);
    ULL s  = mul2_(u, r2);
    ULL s2 = mul2_(s, s);
    ULL q = fma2_(A7, s2, A5);
    q = fma2_(q, s2, A3);
    q = fma2_(q, s2, ONE);
    ULL l1p = mul2_(add2_(s, s), q);
    float mxa = fmaxf(xa, 0.f), mxb = fmaxf(xb, 0.f);
    sp = add2_(pk2(mxa, mxb), l1p);
    float ulo, uhi; upk2(u, ulo, uhi);
    float ga = (xa >= 0.f) ? 1.f : ulo;
    float gb = (xb >= 0.f) ? 1.f : uhi;
    sg = mul2_(r1, pk2(ga, gb));
}

// m16n8k16 fp16 -> f32 MMA (generic-target HMMA)
#define MMA16816(d0,d1,d2,d3,a0,a1,a2,a3,b0,b1) \
    asm volatile("mma.sync.aligned.m16n8k16.row.col.f32.f16.f16.f32 " \
        "{%0,%1,%2,%3}, {%4,%5,%6,%7}, {%8,%9}, {%0,%1,%2,%3};" \
        : "+f"(d0), "+f"(d1), "+f"(d2), "+f"(d3) \
        : "r"(a0), "r"(a1), "r"(a2), "r"(a3), "r"(b0), "r"(b1))

// ---------------- smem layout (pitch 144B keeps all LDS conflict-free) ----
static constexpr int PITCH   = 144;              // 64 fp16 = 128B + 16B pad
static constexpr int A_SPHI  = 0;                // softplus acts fp16 [128 rows]
static constexpr int A_SGHI  = 18432;            // sigmoid  acts fp16
static constexpr int B_PHI   = 36864;            // W2 primal hi [64 n][64 k]
static constexpr int B_PLO   = 46080;            // W2 primal lo
static constexpr int B_THI   = 55296;            // folded tangent (hi only)
static constexpr int W1T_O   = 64512, W1Z0_O = 64768, W1Z1_O = 65024, W1B_O = 65280;
static constexpr int COLW_O  = 65536;            // float4[64] {w2t, b2, w30, w31}
static constexpr int SCAL_O  = 66560;            // float4 {W3[0][0], W3[1][0], b3[0], b3[1]}
static constexpr int SMEM_BYTES = 66576;

__global__ void __launch_bounds__(128, 3) ffjord_mma_kernel(
    const float2* __restrict__ zin, const float* __restrict__ dlp,
    const float* __restrict__ W1, const float* __restrict__ b1,
    const float* __restrict__ W2, const float* __restrict__ b2,
    const float* __restrict__ W3, const float* __restrict__ b3,
    float* __restrict__ out, int B)
{
    extern __shared__ __align__(16) unsigned char smraw[];
    int tid = threadIdx.x;
    int lane = tid & 31, warp = tid >> 5;
    int g = lane >> 2, t4 = lane & 3;

    // ---- stage B weight tiles ----
    if (tid < 64) {
        int j = tid;
        float w30 = W3[1 + j], w31 = W3[66 + j];
        for (int k = 0; k < 64; ++k) {
            float p  = W2[j * 65 + 1 + k];
            float tw = p * fmaf(w30, W1[k * 3 + 1], w31 * W1[k * 3 + 2]);
            __half ph = __float2half_rn(p);
            __half pl = __float2half_rn(p - __half2float(ph));
            __half th = __float2half_rn(tw);
            int off = j * PITCH + k * 2;
            *(__half*)(smraw + B_PHI + off) = ph;
            *(__half*)(smraw + B_PLO + off) = pl;
            *(__half*)(smraw + B_THI + off) = th;
        }
    }
    if (tid < 32) {
        int k = tid;   // unit pair (2k, 2k+1)
        ((ULL*)(smraw + W1T_O))[k]  = pk2(W1[(2 * k) * 3 + 0], W1[(2 * k + 1) * 3 + 0]);
        ((ULL*)(smraw + W1Z0_O))[k] = pk2(W1[(2 * k) * 3 + 1], W1[(2 * k + 1) * 3 + 1]);
        ((ULL*)(smraw + W1Z1_O))[k] = pk2(W1[(2 * k) * 3 + 2], W1[(2 * k + 1) * 3 + 2]);
        ((ULL*)(smraw + W1B_O))[k]  = pk2(b1[2 * k], b1[2 * k + 1]);
    } else if (tid >= 64) {
        int j = tid - 64;
        ((float4*)(smraw + COLW_O))[j] =
            make_float4(W2[j * 65 + 0], b2[j], W3[1 + j], W3[66 + j]);
    }
    if (tid == 0)
        *(float4*)(smraw + SCAL_O) = make_float4(W3[0], W3[65], b3[0], b3[1]);
    __syncthreads();

    const ULL* w1t  = (const ULL*)(smraw + W1T_O);
    const ULL* w1z0 = (const ULL*)(smraw + W1Z0_O);
    const ULL* w1z1 = (const ULL*)(smraw + W1Z1_O);
    const ULL* w1b  = (const ULL*)(smraw + W1B_O);
    const float4* colw = (const float4*)(smraw + COLW_O);
    float4 scal = *(const float4*)(smraw + SCAL_O);

    int gid = blockIdx.x * 128 + tid;
    int gidc = (gid < B) ? gid : (B - 1);
    float2 zv = zin[gidc];
    float z0 = zv.x, z1 = zv.y;
    float lp = dlp[gidc];

    const int rowoff = tid * PITCH;

    const float dt = 0.25f;
    #pragma unroll 1
    for (int step = 0; step < 4; ++step) {
        float tbv = (float)step * dt;
        float acc0 = 0.f, acc1 = 0.f, accl = 0.f;
        float pk0v = 0.f, pk1v = 0.f;
        #pragma unroll 1
        for (int s = 0; s < 4; ++s) {
            float cs = (s == 0) ? 0.0f : ((s == 3) ? dt : 0.5f * dt);
            float ws = (s == 1 || s == 2) ? 2.0f : 1.0f;
            float te = tbv + cs;
            float i0 = fmaf(cs, pk0v, z0);
            float i1 = fmaf(cs, pk1v, z1);

            // ---- layer 1: acts for this thread's sample row -> smem fp16 ----
            ULL tp = pk2(te, te), z0p = pk2(i0, i0), z1p = pk2(i1, i1);
            #pragma unroll 1
            for (int kq = 0; kq < 8; ++kq) {
                u32 sph[4], sgh[4];
                #pragma unroll
                for (int q = 0; q < 4; ++q) {
                    int kp = kq * 4 + q;
                    ULL x = fma2_(w1t[kp], tp, w1b[kp]);
                    x = fma2_(w1z0[kp], z0p, x);
                    x = fma2_(w1z1[kp], z1p, x);
                    float xa, xb; upk2(x, xa, xb);
                    ULL sp, sg; act2(xa, xb, sp, sg);
                    float spa, spb, sga, sgb;
                    upk2(sp, spa, spb); upk2(sg, sga, sgb);
                    sph[q] = f22h2(spa, spb);
                    sgh[q] = f22h2(sga, sgb);
                }
                int co = rowoff + kq * 16;
                *(uint4*)(smraw + A_SPHI + co) = make_uint4(sph[0], sph[1], sph[2], sph[3]);
                *(uint4*)(smraw + A_SGHI + co) = make_uint4(sgh[0], sgh[1], sgh[2], sgh[3]);
            }
            __syncwarp();

            // ---- load A fragments (persistent in registers) ----
            u32 aSPH[32], aSGH[32];
            #pragma unroll
            for (int mm = 0; mm < 2; ++mm) {
                #pragma unroll
                for (int k = 0; k < 4; ++k) {
                    int r0b = (warp * 32 + mm * 16 + g) * PITCH + k * 32 + t4 * 4;
                    int r1b = r0b + 8 * PITCH;
                    int fi = (mm * 4 + k) * 4;
                    aSPH[fi+0] = *(const u32*)(smraw + A_SPHI + r0b);
                    aSPH[fi+1] = *(const u32*)(smraw + A_SPHI + r1b);
                    aSPH[fi+2] = *(const u32*)(smraw + A_SPHI + r0b + 16);
                    aSPH[fi+3] = *(const u32*)(smraw + A_SPHI + r1b + 16);
                    aSGH[fi+0] = *(const u32*)(smraw + A_SGHI + r0b);
                    aSGH[fi+1] = *(const u32*)(smraw + A_SGHI + r1b);
                    aSGH[fi+2] = *(const u32*)(smraw + A_SGHI + r0b + 16);
                    aSGH[fi+3] = *(const u32*)(smraw + A_SGHI + r1b + 16);
                }
            }

            float zr0[4] = {0.f, 0.f, 0.f, 0.f};
            float zr1[4] = {0.f, 0.f, 0.f, 0.f};
            float trr[4] = {0.f, 0.f, 0.f, 0.f};

            #pragma unroll 1
            for (int n = 0; n < 8; ++n) {
                float dP[2][4] = {{0.f,0.f,0.f,0.f},{0.f,0.f,0.f,0.f}};
                float dT[2][4] = {{0.f,0.f,0.f,0.f},{0.f,0.f,0.f,0.f}};
                #pragma unroll
                for (int k = 0; k < 4; ++k) {
                    int bb = (n * 8 + g) * PITCH + k * 32 + t4 * 4;
                    u32 pbh0 = *(const u32*)(smraw + B_PHI + bb);
                    u32 pbh1 = *(const u32*)(smraw + B_PHI + bb + 16);
                    u32 pbl0 = *(const u32*)(smraw + B_PLO + bb);
                    u32 pbl1 = *(const u32*)(smraw + B_PLO + bb + 16);
                    u32 tbh0 = *(const u32*)(smraw + B_THI + bb);
                    u32 tbh1 = *(const u32*)(smraw + B_THI + bb + 16);
                    #pragma unroll
                    for (int mm = 0; mm < 2; ++mm) {
                        int fi = (mm * 4 + k) * 4;
                        MMA16816(dP[mm][0],dP[mm][1],dP[mm][2],dP[mm][3],
                                 aSPH[fi],aSPH[fi+1],aSPH[fi+2],aSPH[fi+3], pbh0,pbh1);
                        MMA16816(dP[mm][0],dP[mm][1],dP[mm][2],dP[mm][3],
                                 aSPH[fi],aSPH[fi+1],aSPH[fi+2],aSPH[fi+3], pbl0,pbl1);
                        MMA16816(dT[mm][0],dT[mm][1],dT[mm][2],dT[mm][3],
                                 aSGH[fi],aSGH[fi+1],aSGH[fi+2],aSGH[fi+3], tbh0,tbh1);
                    }
                }
                // epilogue for this n-tile: cols c0 = n*8+2t4, c0+1
                int c0 = n * 8 + 2 * t4;
                float4 cw0 = colw[c0];
                float4 cw1 = colw[c0 + 1];
                float hb0 = fmaf(cw0.x, te, cw0.y);
                float hb1 = fmaf(cw1.x, te, cw1.y);
                #pragma unroll
                for (int mm = 0; mm < 2; ++mm) {
                    ULL sp2, sg2;
                    float spa, spb, sga, sgb;
                    act2(dP[mm][0] + hb0, dP[mm][1] + hb1, sp2, sg2);
                    upk2(sp2, spa, spb); upk2(sg2, sga, sgb);
                    zr0[2*mm] = fmaf(cw0.z, spa, zr0[2*mm]);
                    zr0[2*mm] = fmaf(cw1.z, spb, zr0[2*mm]);
                    zr1[2*mm] = fmaf(cw0.w, spa, zr1[2*mm]);
                    zr1[2*mm] = fmaf(cw1.w, spb, zr1[2*mm]);
                    trr[2*mm] = fmaf(sga, dT[mm][0], trr[2*mm]);
                    trr[2*mm] = fmaf(sgb, dT[mm][1], trr[2*mm]);
                    act2(dP[mm][2] + hb0, dP[mm][3] + hb1, sp2, sg2);
                    upk2(sp2, spa, spb); upk2(sg2, sga, sgb);
                    zr0[2*mm+1] = fmaf(cw0.z, spa, zr0[2*mm+1]);
                    zr0[2*mm+1] = fmaf(cw1.z, spb, zr0[2*mm+1]);
                    zr1[2*mm+1] = fmaf(cw0.w, spa, zr1[2*mm+1]);
                    zr1[2*mm+1] = fmaf(cw1.w, spb, zr1[2*mm+1]);
                    trr[2*mm+1] = fmaf(sga, dT[mm][2], trr[2*mm+1]);
                    trr[2*mm+1] = fmaf(sgb, dT[mm][3], trr[2*mm+1]);
                }
            }

            // ---- quad reduction via per-warp smem scratch (aliases consumed A rows)
            unsigned char* red = smraw + A_SPHI + warp * 32 * PITCH;
            #pragma unroll
            for (int r4 = 0; r4 < 4; ++r4) {
                int row = r4 * 8 + g;
                float* pr = (float*)(red + row * 48 + t4 * 12);
                pr[0] = zr0[r4]; pr[1] = zr1[r4]; pr[2] = trr[r4];
            }
            __syncwarp();
            float s0 = 0.f, s1 = 0.f, stv = 0.f;
            #pragma unroll
            for (int q = 0; q < 4; ++q) {
                const float* pr = (const float*)(red + lane * 48 + q * 12);
                s0 += pr[0]; s1 += pr[1]; stv += pr[2];
            }
            __syncwarp();

            float k0 = s0 + fmaf(scal.x, te, scal.z);
            float k1 = s1 + fmaf(scal.y, te, scal.w);
            float klv = -stv;

            acc0 = fmaf(ws, k0, acc0);
            acc1 = fmaf(ws, k1, acc1);
            accl = fmaf(ws, klv, accl);
            pk0v = k0; pk1v = k1;
        }
        const float c6 = dt / 6.0f;
        z0 = fmaf(c6, acc0, z0);
        z1 = fmaf(c6, acc1, z1);
        lp = fmaf(c6, accl, lp);
    }

    if (gid < B) {
        reinterpret_cast<float2*>(out)[gid] = make_float2(z0, z1);  // zf: (B,2)
        out[2 * B + gid] = lp;                                      // delta_logpz: (B,1)
    }
}

extern "C" void kernel_launch(void* const* d_in, const int* in_sizes, int n_in,
                              void* d_out, int out_size) {
    const float2* z  = (const float2*)d_in[0];
    const float* dlp = (const float*)d_in[1];
    const float* W1  = (const float*)d_in[2];
    const float* b1  = (const float*)d_in[3];
    const float* W2  = (const float*)d_in[4];
    const float* b2  = (const float*)d_in[5];
    const float* W3  = (const float*)d_in[6];
    const float* b3  = (const float*)d_in[7];
    float* out = (float*)d_out;
    int B = in_sizes[0] / 2;

    // Host-side, enqueues nothing -> graph-capture safe. Idempotent.
    cudaFuncSetAttribute(ffjord_mma_kernel, cudaFuncAttributeMaxDynamicSharedMemorySize,
                         SMEM_BYTES);

    int blocks = (B + 127) / 128;
    ffjord_mma_kernel<<<blocks, 128, SMEM_BYTES>>>(z, dlp, W1, b1, W2, b2, W3, b3, out, B);
}